// round 6
// baseline (speedup 1.0000x reference)
#include <cuda_runtime.h>
#include <cuda_fp16.h>

#define NUx 200000
#define NIx 100000
#define Dx  64
#define Ex  2000000
#define Bx  8192
#define EPSx 1e-12f

#define SB 256
#define SI 8                 // 2048 elements per scan block
#define NW (SB/32)

// ---- static device scratch (no allocation allowed) ----
__device__ int g_deg_u[NUx];
__device__ int g_deg_i[NIx];
__device__ float g_rsd_u[NUx];   // rsqrt(deg)
__device__ float g_rsd_i[NIx];
__device__ int g_off_u[NUx];
__device__ int g_off_i[NIx];
__device__ int g_cur_u[NUx];
__device__ int g_cur_i[NIx];
__device__ int g_bsum_u[128];
__device__ int g_bsum_i[128];
__device__ __align__(16) int2 g_adj_u[Ex];   // per-user: (item, rsd_i[item])
__device__ __align__(16) int2 g_adj_i[Ex];   // per-item: (user, rsd_u[user])

// fp16 feature storage: rows of 32 half2 (64 halves = 128B)
__device__ __align__(256) __half2 g_uf16[(size_t)NUx * 32];
__device__ __align__(256) __half2 g_if16[(size_t)NIx * 32];
__device__ __align__(256) __half2 g_hu16[3][(size_t)NUx * 32];
__device__ __align__(256) __half2 g_hi16[3][(size_t)NIx * 32];

// ---- degree histogram (int) ----
__global__ void k_deg(const int* __restrict__ eu, const int* __restrict__ ei) {
    int t = blockIdx.x * blockDim.x + threadIdx.x;
    if (t < Ex) {
        atomicAdd(&g_deg_u[eu[t]], 1);
        atomicAdd(&g_deg_i[ei[t]], 1);
    }
}

// ---- per-node inverse sqrt degree ----
__global__ void k_rsd() {
    int t = blockIdx.x * blockDim.x + threadIdx.x;
    if (t < NUx) g_rsd_u[t] = rsqrtf((float)max(g_deg_u[t], 1));
    if (t < NIx) g_rsd_i[t] = rsqrtf((float)max(g_deg_i[t], 1));
}

// ---- exclusive scan, stage 1: per-block scan + block sums ----
__global__ void k_scan_blocks(const int* __restrict__ in, int* __restrict__ out,
                              int* __restrict__ bsum, int n) {
    __shared__ int warp_tot[NW];
    int lane = threadIdx.x & 31, wid = threadIdx.x >> 5;
    int base = blockIdx.x * (SB * SI) + threadIdx.x * SI;

    int v[SI];
    int s = 0;
    #pragma unroll
    for (int k = 0; k < SI; ++k) {
        int idx = base + k;
        v[k] = (idx < n) ? in[idx] : 0;
        s += v[k];
    }
    int ps = s;
    #pragma unroll
    for (int o = 1; o < 32; o <<= 1) {
        int t = __shfl_up_sync(0xffffffffu, ps, o);
        if (lane >= o) ps += t;
    }
    if (lane == 31) warp_tot[wid] = ps;
    __syncthreads();
    if (wid == 0) {
        int wt = (lane < NW) ? warp_tot[lane] : 0;
        int wps = wt;
        #pragma unroll
        for (int o = 1; o < NW; o <<= 1) {
            int t = __shfl_up_sync(0xffffffffu, wps, o);
            if (lane >= o) wps += t;
        }
        if (lane < NW) warp_tot[lane] = wps - wt;
    }
    __syncthreads();
    int excl = warp_tot[wid] + (ps - s);
    int run = excl;
    #pragma unroll
    for (int k = 0; k < SI; ++k) {
        int idx = base + k;
        if (idx < n) out[idx] = run;
        run += v[k];
    }
    if (threadIdx.x == SB - 1) bsum[blockIdx.x] = excl + s;
}

// ---- exclusive scan of both block-sum arrays in one launch ----
__global__ void k_scan_small2(int* __restrict__ bu, int nu_,
                              int* __restrict__ bi, int ni_) {
    int* b = blockIdx.x ? bi : bu;
    int n  = blockIdx.x ? ni_ : nu_;
    __shared__ int wt[4];
    int tid = threadIdx.x;
    int lane = tid & 31, wid = tid >> 5;
    int v = (tid < n) ? b[tid] : 0;
    int ps = v;
    #pragma unroll
    for (int o = 1; o < 32; o <<= 1) {
        int t = __shfl_up_sync(0xffffffffu, ps, o);
        if (lane >= o) ps += t;
    }
    if (lane == 31) wt[wid] = ps;
    __syncthreads();
    if (tid == 0) {
        int r = 0;
        #pragma unroll
        for (int k = 0; k < 4; ++k) { int t = wt[k]; wt[k] = r; r += t; }
    }
    __syncthreads();
    if (tid < n) b[tid] = wt[wid] + ps - v;
}

// ---- scan stage 3: add block offsets; also init cursor copy ----
__global__ void k_scan_add(int* __restrict__ out, int* __restrict__ cur,
                           const int* __restrict__ bsum, int n) {
    int base = blockIdx.x * (SB * SI) + threadIdx.x * SI;
    int add = bsum[blockIdx.x];
    #pragma unroll
    for (int k = 0; k < SI; ++k) {
        int idx = base + k;
        if (idx < n) {
            int val = out[idx] + add;
            out[idx] = val;
            cur[idx] = val;
        }
    }
}

// ---- counting-sort fill: (nbr, w=rsd_src[nbr]) per slot ----
__global__ void k_fill(const int* __restrict__ eu, const int* __restrict__ ei) {
    int e = blockIdx.x * blockDim.x + threadIdx.x;
    if (e >= Ex) return;
    int u = eu[e], i = ei[e];
    float wu = g_rsd_u[u];   // weight used when u is the gathered source
    float wi = g_rsd_i[i];   // weight used when i is the gathered source
    int pu = atomicAdd(&g_cur_u[u], 1);
    g_adj_u[pu] = make_int2(i, __float_as_int(wi));
    int pi = atomicAdd(&g_cur_i[i], 1);
    g_adj_i[pi] = make_int2(u, __float_as_int(wu));
}

// ---- convert fp32 inputs to fp16 staging ----
__global__ void k_cvt(const float* __restrict__ uf, const float* __restrict__ itf) {
    int t = blockIdx.x * blockDim.x + threadIdx.x;
    if (t < NUx * 32) {
        float2 f = ((const float2*)uf)[t];
        g_uf16[t] = __float22half2_rn(f);
    } else if (t < (NUx + NIx) * 32) {
        int s = t - NUx * 32;
        float2 f = ((const float2*)itf)[s];
        g_if16[s] = __float22half2_rn(f);
    }
}

// ---- merged both-direction gather-aggregate + fused L2-normalize ----
// warp per dest row; lane = half2 column. One neighbor row per warp-instruction
// (nL=1, fully coalesced). Double-buffered adjacency staging: prefetch batch
// p+32 into registers while gathering batch p from shared.
__global__ void k_agg(const __half2* __restrict__ srcU,
                      const __half2* __restrict__ srcI,
                      __half2* __restrict__ houtU,
                      __half2* __restrict__ houtI) {
    __shared__ int2 sh[NW][32];
    int gw = (blockIdx.x * blockDim.x + threadIdx.x) >> 5;
    int lane = threadIdx.x & 31;
    int wid = threadIdx.x >> 5;
    if (gw >= NIx + NUx) return;

    const __half2* src;
    __half2* hout;
    const int2* adj;
    int beg, end, row;
    if (gw < NIx) {
        row = gw;
        src = srcU; hout = houtI; adj = g_adj_i;
        beg = g_off_i[row];
        end = (row + 1 < NIx) ? g_off_i[row + 1] : Ex;
    } else {
        row = gw - NIx;
        src = srcI; hout = houtU; adj = g_adj_u;
        beg = g_off_u[row];
        end = (row + 1 < NUx) ? g_off_u[row + 1] : Ex;
    }

    float2 acc = make_float2(0.f, 0.f);

    int2 nxt = make_int2(0, 0);
    if (beg + lane < end) nxt = __ldg(&adj[beg + lane]);

    for (int p = beg; p < end; p += 32) {
        sh[wid][lane] = nxt;
        __syncwarp();
        int np = p + 32 + lane;
        if (np < end) nxt = __ldg(&adj[np]);   // prefetch next batch
        int c = min(end - p, 32);
        int j = 0;
        for (; j + 8 <= c; j += 8) {
            #pragma unroll
            for (int q = 0; q < 8; ++q) {
                int2 a = sh[wid][j + q];
                float2 v = __half22float2(__ldg(&src[(size_t)a.x * 32 + lane]));
                float w = __int_as_float(a.y);
                acc.x += w * v.x;
                acc.y += w * v.y;
            }
        }
        for (; j < c; ++j) {
            int2 a = sh[wid][j];
            float2 v = __half22float2(__ldg(&src[(size_t)a.x * 32 + lane]));
            float w = __int_as_float(a.y);
            acc.x += w * v.x;
            acc.y += w * v.y;
        }
        __syncwarp();
    }

    float s = acc.x * acc.x + acc.y * acc.y;
    #pragma unroll
    for (int o = 16; o; o >>= 1) s += __shfl_xor_sync(0xffffffffu, s, o);
    float inv = 1.0f / fmaxf(sqrtf(s), EPSx);

    hout[(size_t)row * 32 + lane] =
        __float22half2_rn(make_float2(acc.x * inv, acc.y * inv));
}

// ---- final gather: e = f + h0 + h1/2 + h2/3 at sampled rows ----
__global__ void k_out(const float* __restrict__ uf, const float* __restrict__ itf,
                      const int* __restrict__ users, const int* __restrict__ pos,
                      const int* __restrict__ neg, float* __restrict__ out) {
    unsigned t = blockIdx.x * blockDim.x + threadIdx.x;
    unsigned r = t >> 4;
    unsigned lane = t & 15u;          // 16 lanes x 4 cols = 64
    if (r >= 3u * Bx) return;
    unsigned grp = r / Bx, idx = r % Bx;

    const float* base;
    const __half2 *h0, *h1, *h2;
    size_t row;
    if (grp == 0) {
        row = (size_t)users[idx];
        base = uf + row * Dx;
        h0 = g_hu16[0] + row * 32; h1 = g_hu16[1] + row * 32; h2 = g_hu16[2] + row * 32;
    } else {
        row = (size_t)((grp == 1) ? pos[idx] : neg[idx]);
        base = itf + row * Dx;
        h0 = g_hi16[0] + row * 32; h1 = g_hi16[1] + row * 32; h2 = g_hi16[2] + row * 32;
    }

    float4 f = *(const float4*)(base + lane * 4);
    float2 a0 = __half22float2(h0[lane * 2]), b0 = __half22float2(h0[lane * 2 + 1]);
    float2 a1 = __half22float2(h1[lane * 2]), b1 = __half22float2(h1[lane * 2 + 1]);
    float2 a2 = __half22float2(h2[lane * 2]), b2 = __half22float2(h2[lane * 2 + 1]);

    const float c1 = 0.5f, c2 = 1.0f / 3.0f;
    f.x += a0.x + c1 * a1.x + c2 * a2.x;
    f.y += a0.y + c1 * a1.y + c2 * a2.y;
    f.z += b0.x + c1 * b1.x + c2 * b2.x;
    f.w += b0.y + c1 * b1.y + c2 * b2.y;

    *(float4*)(out + (size_t)r * Dx + lane * 4) = f;
}

extern "C" void kernel_launch(void* const* d_in, const int* in_sizes, int n_in,
                              void* d_out, int out_size) {
    const float* uf  = (const float*)d_in[0];
    const float* itf = (const float*)d_in[1];
    const int*   eu  = (const int*)d_in[2];
    const int*   ei  = (const int*)d_in[3];
    const int*   usr = (const int*)d_in[4];
    const int*   pos = (const int*)d_in[5];
    const int*   neg = (const int*)d_in[6];
    float* out = (float*)d_out;

    void *p_deg_u, *p_deg_i, *p_off_u, *p_off_i, *p_cur_u, *p_cur_i;
    void *p_bsum_u, *p_bsum_i;
    void *p_uf16, *p_if16, *p_hu[3], *p_hi[3];
    cudaGetSymbolAddress(&p_deg_u, g_deg_u);
    cudaGetSymbolAddress(&p_deg_i, g_deg_i);
    cudaGetSymbolAddress(&p_off_u, g_off_u);
    cudaGetSymbolAddress(&p_off_i, g_off_i);
    cudaGetSymbolAddress(&p_cur_u, g_cur_u);
    cudaGetSymbolAddress(&p_cur_i, g_cur_i);
    cudaGetSymbolAddress(&p_bsum_u, g_bsum_u);
    cudaGetSymbolAddress(&p_bsum_i, g_bsum_i);
    cudaGetSymbolAddress(&p_uf16, g_uf16);
    cudaGetSymbolAddress(&p_if16, g_if16);
    {
        void* tmp;
        cudaGetSymbolAddress(&tmp, g_hu16);
        for (int k = 0; k < 3; ++k) p_hu[k] = (char*)tmp + (size_t)k * NUx * 32 * sizeof(__half2);
        cudaGetSymbolAddress(&tmp, g_hi16);
        for (int k = 0; k < 3; ++k) p_hi[k] = (char*)tmp + (size_t)k * NIx * 32 * sizeof(__half2);
    }

    const int scanb_u = (NUx + SB * SI - 1) / (SB * SI);   // 98
    const int scanb_i = (NIx + SB * SI - 1) / (SB * SI);   // 49

    // ---- CSR build + fp16 input staging ----
    cudaMemsetAsync(p_deg_u, 0, NUx * sizeof(int));
    cudaMemsetAsync(p_deg_i, 0, NIx * sizeof(int));
    k_deg<<<(Ex + 255) / 256, 256>>>(eu, ei);
    k_cvt<<<((NUx + NIx) * 32 + 255) / 256, 256>>>(uf, itf);
    k_rsd<<<(NUx + 255) / 256, 256>>>();
    k_scan_blocks<<<scanb_u, SB>>>((const int*)p_deg_u, (int*)p_off_u, (int*)p_bsum_u, NUx);
    k_scan_blocks<<<scanb_i, SB>>>((const int*)p_deg_i, (int*)p_off_i, (int*)p_bsum_i, NIx);
    k_scan_small2<<<2, 128>>>((int*)p_bsum_u, scanb_u, (int*)p_bsum_i, scanb_i);
    k_scan_add<<<scanb_u, SB>>>((int*)p_off_u, (int*)p_cur_u, (const int*)p_bsum_u, NUx);
    k_scan_add<<<scanb_i, SB>>>((int*)p_off_i, (int*)p_cur_i, (const int*)p_bsum_i, NIx);
    k_fill<<<(Ex + 255) / 256, 256>>>(eu, ei);

    const unsigned gagg = (unsigned)(((size_t)(NUx + NIx) * 32 + 255) / 256);

    // ---- 3 propagation layers (both directions merged per launch) ----
    k_agg<<<gagg, 256>>>((const __half2*)p_uf16, (const __half2*)p_if16,
                         (__half2*)p_hu[0], (__half2*)p_hi[0]);
    k_agg<<<gagg, 256>>>((const __half2*)p_hu[0], (const __half2*)p_hi[0],
                         (__half2*)p_hu[1], (__half2*)p_hi[1]);
    k_agg<<<gagg, 256>>>((const __half2*)p_hu[1], (const __half2*)p_hi[1],
                         (__half2*)p_hu[2], (__half2*)p_hi[2]);

    // ---- output gather (e computed on the fly) ----
    k_out<<<(3 * Bx * 16 + 255) / 256, 256>>>(uf, itf, usr, pos, neg, out);
}

// round 7
// speedup vs baseline: 1.1132x; 1.1132x over previous
#include <cuda_runtime.h>
#include <cuda_fp16.h>

#define NUx 200000
#define NIx 100000
#define Dx  64
#define Ex  2000000
#define Bx  8192
#define EPSx 1e-12f

#define PAD4(x) (((x) + 3) & ~3)

#define SB 256
#define SI 8                 // 2048 elements per scan block
#define NW (SB/32)

// ---- static device scratch (no allocation allowed) ----
__device__ int g_deg_u[NUx];
__device__ int g_deg_i[NIx];
__device__ float g_rsd_u[NUx];   // rsqrt(deg)
__device__ float g_rsd_i[NIx];
__device__ int g_off_u[NUx];
__device__ int g_off_i[NIx];
__device__ int g_cur_u[NUx];
__device__ int g_cur_i[NIx];
__device__ int g_bsum_u[128];
__device__ int g_bsum_i[128];
// padded adjacency: worst case E + 3*Nrows entries
__device__ __align__(16) int2 g_adj_u[Ex + 3 * NUx];  // per-user: (item, rsd_i[item])
__device__ __align__(16) int2 g_adj_i[Ex + 3 * NIx];  // per-item: (user, rsd_u[user])

// fp16 feature storage: rows of 32 half2 (64 halves = 128B)
__device__ __align__(256) __half2 g_uf16[(size_t)NUx * 32];
__device__ __align__(256) __half2 g_if16[(size_t)NIx * 32];
__device__ __align__(256) __half2 g_hu16[3][(size_t)NUx * 32];
__device__ __align__(256) __half2 g_hi16[3][(size_t)NIx * 32];

// ---- degree histogram (int) ----
__global__ void k_deg(const int* __restrict__ eu, const int* __restrict__ ei) {
    int t = blockIdx.x * blockDim.x + threadIdx.x;
    if (t < Ex) {
        atomicAdd(&g_deg_u[eu[t]], 1);
        atomicAdd(&g_deg_i[ei[t]], 1);
    }
}

// ---- per-node inverse sqrt degree ----
__global__ void k_rsd() {
    int t = blockIdx.x * blockDim.x + threadIdx.x;
    if (t < NUx) g_rsd_u[t] = rsqrtf((float)max(g_deg_u[t], 1));
    if (t < NIx) g_rsd_i[t] = rsqrtf((float)max(g_deg_i[t], 1));
}

// ---- exclusive scan of PADDED degrees, stage 1 ----
__global__ void k_scan_blocks(const int* __restrict__ in, int* __restrict__ out,
                              int* __restrict__ bsum, int n) {
    __shared__ int warp_tot[NW];
    int lane = threadIdx.x & 31, wid = threadIdx.x >> 5;
    int base = blockIdx.x * (SB * SI) + threadIdx.x * SI;

    int v[SI];
    int s = 0;
    #pragma unroll
    for (int k = 0; k < SI; ++k) {
        int idx = base + k;
        v[k] = (idx < n) ? PAD4(in[idx]) : 0;
        s += v[k];
    }
    int ps = s;
    #pragma unroll
    for (int o = 1; o < 32; o <<= 1) {
        int t = __shfl_up_sync(0xffffffffu, ps, o);
        if (lane >= o) ps += t;
    }
    if (lane == 31) warp_tot[wid] = ps;
    __syncthreads();
    if (wid == 0) {
        int wt = (lane < NW) ? warp_tot[lane] : 0;
        int wps = wt;
        #pragma unroll
        for (int o = 1; o < NW; o <<= 1) {
            int t = __shfl_up_sync(0xffffffffu, wps, o);
            if (lane >= o) wps += t;
        }
        if (lane < NW) warp_tot[lane] = wps - wt;
    }
    __syncthreads();
    int excl = warp_tot[wid] + (ps - s);
    int run = excl;
    #pragma unroll
    for (int k = 0; k < SI; ++k) {
        int idx = base + k;
        if (idx < n) out[idx] = run;
        run += v[k];
    }
    if (threadIdx.x == SB - 1) bsum[blockIdx.x] = excl + s;
}

// ---- exclusive scan of both block-sum arrays in one launch ----
__global__ void k_scan_small2(int* __restrict__ bu, int nu_,
                              int* __restrict__ bi, int ni_) {
    int* b = blockIdx.x ? bi : bu;
    int n  = blockIdx.x ? ni_ : nu_;
    __shared__ int wt[4];
    int tid = threadIdx.x;
    int lane = tid & 31, wid = tid >> 5;
    int v = (tid < n) ? b[tid] : 0;
    int ps = v;
    #pragma unroll
    for (int o = 1; o < 32; o <<= 1) {
        int t = __shfl_up_sync(0xffffffffu, ps, o);
        if (lane >= o) ps += t;
    }
    if (lane == 31) wt[wid] = ps;
    __syncthreads();
    if (tid == 0) {
        int r = 0;
        #pragma unroll
        for (int k = 0; k < 4; ++k) { int t = wt[k]; wt[k] = r; r += t; }
    }
    __syncthreads();
    if (tid < n) b[tid] = wt[wid] + ps - v;
}

// ---- scan stage 3: add block offsets; also init cursor copy ----
__global__ void k_scan_add(int* __restrict__ out, int* __restrict__ cur,
                           const int* __restrict__ bsum, int n) {
    int base = blockIdx.x * (SB * SI) + threadIdx.x * SI;
    int add = bsum[blockIdx.x];
    #pragma unroll
    for (int k = 0; k < SI; ++k) {
        int idx = base + k;
        if (idx < n) {
            int val = out[idx] + add;
            out[idx] = val;
            cur[idx] = val;
        }
    }
}

// ---- write (0,0) pad entries into slots [off+deg, off+pad4(deg)) ----
__global__ void k_padfill() {
    int t = blockIdx.x * blockDim.x + threadIdx.x;
    if (t < NUx) {
        int d = g_deg_u[t], o = g_off_u[t];
        int pd = PAD4(d);
        for (int k = d; k < pd; ++k) g_adj_u[o + k] = make_int2(0, 0);
    }
    if (t < NIx) {
        int d = g_deg_i[t], o = g_off_i[t];
        int pd = PAD4(d);
        for (int k = d; k < pd; ++k) g_adj_i[o + k] = make_int2(0, 0);
    }
}

// ---- counting-sort fill: (nbr, w=rsd_src[nbr]) per slot ----
__global__ void k_fill(const int* __restrict__ eu, const int* __restrict__ ei) {
    int e = blockIdx.x * blockDim.x + threadIdx.x;
    if (e >= Ex) return;
    int u = eu[e], i = ei[e];
    float wu = g_rsd_u[u];   // weight when u is the gathered source
    float wi = g_rsd_i[i];   // weight when i is the gathered source
    int pu = atomicAdd(&g_cur_u[u], 1);
    g_adj_u[pu] = make_int2(i, __float_as_int(wi));
    int pi = atomicAdd(&g_cur_i[i], 1);
    g_adj_i[pi] = make_int2(u, __float_as_int(wu));
}

// ---- convert fp32 inputs to fp16 staging ----
__global__ void k_cvt(const float* __restrict__ uf, const float* __restrict__ itf) {
    int t = blockIdx.x * blockDim.x + threadIdx.x;
    if (t < NUx * 32) {
        float2 f = ((const float2*)uf)[t];
        g_uf16[t] = __float22half2_rn(f);
    } else if (t < (NUx + NIx) * 32) {
        int s = t - NUx * 32;
        float2 f = ((const float2*)itf)[s];
        g_if16[s] = __float22half2_rn(f);
    }
}

// ---- merged both-direction gather-aggregate + fused L2-normalize ----
// warp per dest row; lane = half2 column. One neighbor row per warp-instruction
// (nL=1, fully coalesced). Rows are padded to multiples of 4 with (0,0)
// entries, so the gather loop is pure unroll-4 batches (no serial tail).
// Adjacency staged with __ldcs (evict-first) to protect feature residency.
__global__ void k_agg(const __half2* __restrict__ srcU,
                      const __half2* __restrict__ srcI,
                      __half2* __restrict__ houtU,
                      __half2* __restrict__ houtI) {
    __shared__ int2 sh[NW][32];
    int gw = (blockIdx.x * blockDim.x + threadIdx.x) >> 5;
    int lane = threadIdx.x & 31;
    int wid = threadIdx.x >> 5;
    if (gw >= NIx + NUx) return;

    const __half2* src;
    __half2* hout;
    const int2* adj;
    int beg, end, row;
    if (gw < NIx) {
        row = gw;
        src = srcU; hout = houtI; adj = g_adj_i;
        beg = g_off_i[row];
        end = (row + 1 < NIx) ? g_off_i[row + 1] : beg + PAD4(g_deg_i[row]);
    } else {
        row = gw - NIx;
        src = srcI; hout = houtU; adj = g_adj_u;
        beg = g_off_u[row];
        end = (row + 1 < NUx) ? g_off_u[row + 1] : beg + PAD4(g_deg_u[row]);
    }

    float2 acc = make_float2(0.f, 0.f);

    for (int p = beg; p < end; p += 32) {
        int idx = p + lane;
        if (idx < end) sh[wid][lane] = __ldcs(&adj[idx]);
        __syncwarp();
        int c = min(end - p, 32);           // multiple of 4
        for (int j = 0; j < c; j += 4) {
            int2 a0 = sh[wid][j + 0];
            int2 a1 = sh[wid][j + 1];
            int2 a2 = sh[wid][j + 2];
            int2 a3 = sh[wid][j + 3];
            float2 v0 = __half22float2(src[(size_t)a0.x * 32 + lane]);
            float2 v1 = __half22float2(src[(size_t)a1.x * 32 + lane]);
            float2 v2 = __half22float2(src[(size_t)a2.x * 32 + lane]);
            float2 v3 = __half22float2(src[(size_t)a3.x * 32 + lane]);
            float w0 = __int_as_float(a0.y);
            float w1 = __int_as_float(a1.y);
            float w2 = __int_as_float(a2.y);
            float w3 = __int_as_float(a3.y);
            acc.x += w0 * v0.x; acc.y += w0 * v0.y;
            acc.x += w1 * v1.x; acc.y += w1 * v1.y;
            acc.x += w2 * v2.x; acc.y += w2 * v2.y;
            acc.x += w3 * v3.x; acc.y += w3 * v3.y;
        }
        __syncwarp();
    }

    float s = acc.x * acc.x + acc.y * acc.y;
    #pragma unroll
    for (int o = 16; o; o >>= 1) s += __shfl_xor_sync(0xffffffffu, s, o);
    float inv = 1.0f / fmaxf(sqrtf(s), EPSx);

    hout[(size_t)row * 32 + lane] =
        __float22half2_rn(make_float2(acc.x * inv, acc.y * inv));
}

// ---- final gather: e = f + h0 + h1/2 + h2/3 at sampled rows ----
__global__ void k_out(const float* __restrict__ uf, const float* __restrict__ itf,
                      const int* __restrict__ users, const int* __restrict__ pos,
                      const int* __restrict__ neg, float* __restrict__ out) {
    unsigned t = blockIdx.x * blockDim.x + threadIdx.x;
    unsigned r = t >> 4;
    unsigned lane = t & 15u;          // 16 lanes x 4 cols = 64
    if (r >= 3u * Bx) return;
    unsigned grp = r / Bx, idx = r % Bx;

    const float* base;
    const __half2 *h0, *h1, *h2;
    size_t row;
    if (grp == 0) {
        row = (size_t)users[idx];
        base = uf + row * Dx;
        h0 = g_hu16[0] + row * 32; h1 = g_hu16[1] + row * 32; h2 = g_hu16[2] + row * 32;
    } else {
        row = (size_t)((grp == 1) ? pos[idx] : neg[idx]);
        base = itf + row * Dx;
        h0 = g_hi16[0] + row * 32; h1 = g_hi16[1] + row * 32; h2 = g_hi16[2] + row * 32;
    }

    float4 f = *(const float4*)(base + lane * 4);
    float2 a0 = __half22float2(h0[lane * 2]), b0 = __half22float2(h0[lane * 2 + 1]);
    float2 a1 = __half22float2(h1[lane * 2]), b1 = __half22float2(h1[lane * 2 + 1]);
    float2 a2 = __half22float2(h2[lane * 2]), b2 = __half22float2(h2[lane * 2 + 1]);

    const float c1 = 0.5f, c2 = 1.0f / 3.0f;
    f.x += a0.x + c1 * a1.x + c2 * a2.x;
    f.y += a0.y + c1 * a1.y + c2 * a2.y;
    f.z += b0.x + c1 * b1.x + c2 * b2.x;
    f.w += b0.y + c1 * b1.y + c2 * b2.y;

    *(float4*)(out + (size_t)r * Dx + lane * 4) = f;
}

extern "C" void kernel_launch(void* const* d_in, const int* in_sizes, int n_in,
                              void* d_out, int out_size) {
    const float* uf  = (const float*)d_in[0];
    const float* itf = (const float*)d_in[1];
    const int*   eu  = (const int*)d_in[2];
    const int*   ei  = (const int*)d_in[3];
    const int*   usr = (const int*)d_in[4];
    const int*   pos = (const int*)d_in[5];
    const int*   neg = (const int*)d_in[6];
    float* out = (float*)d_out;

    void *p_deg_u, *p_deg_i, *p_off_u, *p_off_i, *p_cur_u, *p_cur_i;
    void *p_bsum_u, *p_bsum_i;
    void *p_uf16, *p_if16, *p_hu[3], *p_hi[3];
    cudaGetSymbolAddress(&p_deg_u, g_deg_u);
    cudaGetSymbolAddress(&p_deg_i, g_deg_i);
    cudaGetSymbolAddress(&p_off_u, g_off_u);
    cudaGetSymbolAddress(&p_off_i, g_off_i);
    cudaGetSymbolAddress(&p_cur_u, g_cur_u);
    cudaGetSymbolAddress(&p_cur_i, g_cur_i);
    cudaGetSymbolAddress(&p_bsum_u, g_bsum_u);
    cudaGetSymbolAddress(&p_bsum_i, g_bsum_i);
    cudaGetSymbolAddress(&p_uf16, g_uf16);
    cudaGetSymbolAddress(&p_if16, g_if16);
    {
        void* tmp;
        cudaGetSymbolAddress(&tmp, g_hu16);
        for (int k = 0; k < 3; ++k) p_hu[k] = (char*)tmp + (size_t)k * NUx * 32 * sizeof(__half2);
        cudaGetSymbolAddress(&tmp, g_hi16);
        for (int k = 0; k < 3; ++k) p_hi[k] = (char*)tmp + (size_t)k * NIx * 32 * sizeof(__half2);
    }

    const int scanb_u = (NUx + SB * SI - 1) / (SB * SI);   // 98
    const int scanb_i = (NIx + SB * SI - 1) / (SB * SI);   // 49

    // ---- CSR build (padded) + fp16 input staging ----
    cudaMemsetAsync(p_deg_u, 0, NUx * sizeof(int));
    cudaMemsetAsync(p_deg_i, 0, NIx * sizeof(int));
    k_deg<<<(Ex + 255) / 256, 256>>>(eu, ei);
    k_cvt<<<((NUx + NIx) * 32 + 255) / 256, 256>>>(uf, itf);
    k_rsd<<<(NUx + 255) / 256, 256>>>();
    k_scan_blocks<<<scanb_u, SB>>>((const int*)p_deg_u, (int*)p_off_u, (int*)p_bsum_u, NUx);
    k_scan_blocks<<<scanb_i, SB>>>((const int*)p_deg_i, (int*)p_off_i, (int*)p_bsum_i, NIx);
    k_scan_small2<<<2, 128>>>((int*)p_bsum_u, scanb_u, (int*)p_bsum_i, scanb_i);
    k_scan_add<<<scanb_u, SB>>>((int*)p_off_u, (int*)p_cur_u, (const int*)p_bsum_u, NUx);
    k_scan_add<<<scanb_i, SB>>>((int*)p_off_i, (int*)p_cur_i, (const int*)p_bsum_i, NIx);
    k_padfill<<<(NUx + 255) / 256, 256>>>();
    k_fill<<<(Ex + 255) / 256, 256>>>(eu, ei);

    const unsigned gagg = (unsigned)(((size_t)(NUx + NIx) * 32 + 255) / 256);

    // ---- 3 propagation layers (both directions merged per launch) ----
    k_agg<<<gagg, 256>>>((const __half2*)p_uf16, (const __half2*)p_if16,
                         (__half2*)p_hu[0], (__half2*)p_hi[0]);
    k_agg<<<gagg, 256>>>((const __half2*)p_hu[0], (const __half2*)p_hi[0],
                         (__half2*)p_hu[1], (__half2*)p_hi[1]);
    k_agg<<<gagg, 256>>>((const __half2*)p_hu[1], (const __half2*)p_hi[1],
                         (__half2*)p_hu[2], (__half2*)p_hi[2]);

    // ---- output gather (e computed on the fly) ----
    k_out<<<(3 * Bx * 16 + 255) / 256, 256>>>(uf, itf, usr, pos, neg, out);
}

// round 8
// speedup vs baseline: 1.2511x; 1.1239x over previous
#include <cuda_runtime.h>
#include <cuda_fp16.h>

#define NUx 200000
#define NIx 100000
#define Dx  64
#define Ex  2000000
#define Bx  8192
#define EPSx 1e-12f

#define SB 256
#define SI 8                 // 2048 elements per scan block
#define NW (SB/32)

// ---- static device scratch (no allocation allowed) ----
__device__ int g_deg_u[NUx];
__device__ int g_deg_i[NIx];
__device__ int g_off_u[NUx];
__device__ int g_off_i[NIx];
__device__ int g_cur_u[NUx];
__device__ int g_cur_i[NIx];
__device__ int g_bsum_u[128];
__device__ int g_bsum_i[128];
__device__ __align__(16) int2 g_adj_u[Ex];   // per-user: (item, norm_e)
__device__ __align__(16) int2 g_adj_i[Ex];   // per-item: (user, norm_e)

// fp16 feature storage: rows of 32 half2 (64 halves = 128B)
__device__ __align__(256) __half2 g_uf16[(size_t)NUx * 32];
__device__ __align__(256) __half2 g_if16[(size_t)NIx * 32];
__device__ __align__(256) __half2 g_hu16[3][(size_t)NUx * 32];
__device__ __align__(256) __half2 g_hi16[3][(size_t)NIx * 32];

// ---- degree histogram (int) ----
__global__ void k_deg(const int* __restrict__ eu, const int* __restrict__ ei) {
    int t = blockIdx.x * blockDim.x + threadIdx.x;
    if (t < Ex) {
        atomicAdd(&g_deg_u[eu[t]], 1);
        atomicAdd(&g_deg_i[ei[t]], 1);
    }
}

// ---- exclusive scan, stage 1: per-block scan + block sums ----
__global__ void k_scan_blocks(const int* __restrict__ in, int* __restrict__ out,
                              int* __restrict__ bsum, int n) {
    __shared__ int warp_tot[NW];
    int lane = threadIdx.x & 31, wid = threadIdx.x >> 5;
    int base = blockIdx.x * (SB * SI) + threadIdx.x * SI;

    int v[SI];
    int s = 0;
    #pragma unroll
    for (int k = 0; k < SI; ++k) {
        int idx = base + k;
        v[k] = (idx < n) ? in[idx] : 0;
        s += v[k];
    }
    int ps = s;
    #pragma unroll
    for (int o = 1; o < 32; o <<= 1) {
        int t = __shfl_up_sync(0xffffffffu, ps, o);
        if (lane >= o) ps += t;
    }
    if (lane == 31) warp_tot[wid] = ps;
    __syncthreads();
    if (wid == 0) {
        int wt = (lane < NW) ? warp_tot[lane] : 0;
        int wps = wt;
        #pragma unroll
        for (int o = 1; o < NW; o <<= 1) {
            int t = __shfl_up_sync(0xffffffffu, wps, o);
            if (lane >= o) wps += t;
        }
        if (lane < NW) warp_tot[lane] = wps - wt;
    }
    __syncthreads();
    int excl = warp_tot[wid] + (ps - s);
    int run = excl;
    #pragma unroll
    for (int k = 0; k < SI; ++k) {
        int idx = base + k;
        if (idx < n) out[idx] = run;
        run += v[k];
    }
    if (threadIdx.x == SB - 1) bsum[blockIdx.x] = excl + s;
}

// ---- exclusive scan of both block-sum arrays in one launch ----
__global__ void k_scan_small2(int* __restrict__ bu, int nu_,
                              int* __restrict__ bi, int ni_) {
    int* b = blockIdx.x ? bi : bu;
    int n  = blockIdx.x ? ni_ : nu_;
    __shared__ int wt[4];
    int tid = threadIdx.x;
    int lane = tid & 31, wid = tid >> 5;
    int v = (tid < n) ? b[tid] : 0;
    int ps = v;
    #pragma unroll
    for (int o = 1; o < 32; o <<= 1) {
        int t = __shfl_up_sync(0xffffffffu, ps, o);
        if (lane >= o) ps += t;
    }
    if (lane == 31) wt[wid] = ps;
    __syncthreads();
    if (tid == 0) {
        int r = 0;
        #pragma unroll
        for (int k = 0; k < 4; ++k) { int t = wt[k]; wt[k] = r; r += t; }
    }
    __syncthreads();
    if (tid < n) b[tid] = wt[wid] + ps - v;
}

// ---- scan stage 3: add block offsets; also init cursor copy ----
__global__ void k_scan_add(int* __restrict__ out, int* __restrict__ cur,
                           const int* __restrict__ bsum, int n) {
    int base = blockIdx.x * (SB * SI) + threadIdx.x * SI;
    int add = bsum[blockIdx.x];
    #pragma unroll
    for (int k = 0; k < SI; ++k) {
        int idx = base + k;
        if (idx < n) {
            int val = out[idx] + add;
            out[idx] = val;
            cur[idx] = val;
        }
    }
}

// ---- counting-sort fill of both adjacency lists + per-edge norm ----
__global__ void k_fill(const int* __restrict__ eu, const int* __restrict__ ei) {
    int e = blockIdx.x * blockDim.x + threadIdx.x;
    if (e >= Ex) return;
    int u = eu[e], i = ei[e];
    float w = rsqrtf((float)(g_deg_u[u] * g_deg_i[i]));
    int wb = __float_as_int(w);
    int pu = atomicAdd(&g_cur_u[u], 1);
    g_adj_u[pu] = make_int2(i, wb);
    int pi = atomicAdd(&g_cur_i[i], 1);
    g_adj_i[pi] = make_int2(u, wb);
}

// ---- convert fp32 inputs to fp16 staging ----
__global__ void k_cvt(const float* __restrict__ uf, const float* __restrict__ itf) {
    int t = blockIdx.x * blockDim.x + threadIdx.x;
    if (t < NUx * 32) {
        float2 f = ((const float2*)uf)[t];
        g_uf16[t] = __float22half2_rn(f);
    } else if (t < (NUx + NIx) * 32) {
        int s = t - NUx * 32;
        float2 f = ((const float2*)itf)[s];
        g_if16[s] = __float22half2_rn(f);
    }
}

// ---- merged both-direction gather-aggregate + fused L2-normalize ----
// ONE WARP PER TWO CONSECUTIVE DEST ROWS. Their CSR ranges are adjacent, so
// the warp stages [off[2k], off[2k+2]) as one contiguous stream; the row-split
// test (p+j < mid) is warp-uniform. Amortizes offset loads, staging waits, and
// epilogue over 2 rows; two independent accumulator chains raise MLP.
__global__ void k_agg(const __half2* __restrict__ srcU,
                      const __half2* __restrict__ srcI,
                      __half2* __restrict__ houtU,
                      __half2* __restrict__ houtI) {
    __shared__ int2 sh[NW][32];
    int gw = (blockIdx.x * blockDim.x + threadIdx.x) >> 5;   // pair index
    int lane = threadIdx.x & 31;
    int wid = threadIdx.x >> 5;
    const int PI = NIx / 2, PU = NUx / 2;
    if (gw >= PI + PU) return;

    const __half2* src;
    __half2* hout;
    const int2* adj;
    const int* off;
    int row0, nrows;
    if (gw < PI) {
        row0 = gw * 2; nrows = NIx;
        src = srcU; hout = houtI; adj = g_adj_i; off = g_off_i;
    } else {
        row0 = (gw - PI) * 2; nrows = NUx;
        src = srcI; hout = houtU; adj = g_adj_u; off = g_off_u;
    }

    int beg = off[row0];
    int mid = off[row0 + 1];
    int end = (row0 + 2 < nrows) ? off[row0 + 2] : Ex;

    float2 acc0 = make_float2(0.f, 0.f);
    float2 acc1 = make_float2(0.f, 0.f);

    for (int p = beg; p < end; p += 32) {
        int idx = p + lane;
        if (idx < end) sh[wid][lane] = adj[idx];
        __syncwarp();
        int c = min(end - p, 32);
        #pragma unroll 4
        for (int j = 0; j < c; ++j) {
            int2 a = sh[wid][j];
            float2 v = __half22float2(src[(size_t)a.x * 32 + lane]);
            float w = __int_as_float(a.y);
            if (p + j < mid) {                 // warp-uniform branch
                acc0.x += w * v.x; acc0.y += w * v.y;
            } else {
                acc1.x += w * v.x; acc1.y += w * v.y;
            }
        }
        __syncwarp();
    }

    float s0 = acc0.x * acc0.x + acc0.y * acc0.y;
    float s1 = acc1.x * acc1.x + acc1.y * acc1.y;
    #pragma unroll
    for (int o = 16; o; o >>= 1) {
        s0 += __shfl_xor_sync(0xffffffffu, s0, o);
        s1 += __shfl_xor_sync(0xffffffffu, s1, o);
    }
    float inv0 = 1.0f / fmaxf(sqrtf(s0), EPSx);
    float inv1 = 1.0f / fmaxf(sqrtf(s1), EPSx);

    hout[(size_t)row0 * 32 + lane] =
        __float22half2_rn(make_float2(acc0.x * inv0, acc0.y * inv0));
    hout[(size_t)(row0 + 1) * 32 + lane] =
        __float22half2_rn(make_float2(acc1.x * inv1, acc1.y * inv1));
}

// ---- final gather: e = f + h0 + h1/2 + h2/3 at sampled rows ----
__global__ void k_out(const float* __restrict__ uf, const float* __restrict__ itf,
                      const int* __restrict__ users, const int* __restrict__ pos,
                      const int* __restrict__ neg, float* __restrict__ out) {
    unsigned t = blockIdx.x * blockDim.x + threadIdx.x;
    unsigned r = t >> 4;
    unsigned lane = t & 15u;          // 16 lanes x 4 cols = 64
    if (r >= 3u * Bx) return;
    unsigned grp = r / Bx, idx = r % Bx;

    const float* base;
    const __half2 *h0, *h1, *h2;
    size_t row;
    if (grp == 0) {
        row = (size_t)users[idx];
        base = uf + row * Dx;
        h0 = g_hu16[0] + row * 32; h1 = g_hu16[1] + row * 32; h2 = g_hu16[2] + row * 32;
    } else {
        row = (size_t)((grp == 1) ? pos[idx] : neg[idx]);
        base = itf + row * Dx;
        h0 = g_hi16[0] + row * 32; h1 = g_hi16[1] + row * 32; h2 = g_hi16[2] + row * 32;
    }

    float4 f = *(const float4*)(base + lane * 4);
    float2 a0 = __half22float2(h0[lane * 2]), b0 = __half22float2(h0[lane * 2 + 1]);
    float2 a1 = __half22float2(h1[lane * 2]), b1 = __half22float2(h1[lane * 2 + 1]);
    float2 a2 = __half22float2(h2[lane * 2]), b2 = __half22float2(h2[lane * 2 + 1]);

    const float c1 = 0.5f, c2 = 1.0f / 3.0f;
    f.x += a0.x + c1 * a1.x + c2 * a2.x;
    f.y += a0.y + c1 * a1.y + c2 * a2.y;
    f.z += b0.x + c1 * b1.x + c2 * b2.x;
    f.w += b0.y + c1 * b1.y + c2 * b2.y;

    *(float4*)(out + (size_t)r * Dx + lane * 4) = f;
}

extern "C" void kernel_launch(void* const* d_in, const int* in_sizes, int n_in,
                              void* d_out, int out_size) {
    const float* uf  = (const float*)d_in[0];
    const float* itf = (const float*)d_in[1];
    const int*   eu  = (const int*)d_in[2];
    const int*   ei  = (const int*)d_in[3];
    const int*   usr = (const int*)d_in[4];
    const int*   pos = (const int*)d_in[5];
    const int*   neg = (const int*)d_in[6];
    float* out = (float*)d_out;

    void *p_deg_u, *p_deg_i, *p_off_u, *p_off_i, *p_cur_u, *p_cur_i;
    void *p_bsum_u, *p_bsum_i;
    void *p_uf16, *p_if16, *p_hu[3], *p_hi[3];
    cudaGetSymbolAddress(&p_deg_u, g_deg_u);
    cudaGetSymbolAddress(&p_deg_i, g_deg_i);
    cudaGetSymbolAddress(&p_off_u, g_off_u);
    cudaGetSymbolAddress(&p_off_i, g_off_i);
    cudaGetSymbolAddress(&p_cur_u, g_cur_u);
    cudaGetSymbolAddress(&p_cur_i, g_cur_i);
    cudaGetSymbolAddress(&p_bsum_u, g_bsum_u);
    cudaGetSymbolAddress(&p_bsum_i, g_bsum_i);
    cudaGetSymbolAddress(&p_uf16, g_uf16);
    cudaGetSymbolAddress(&p_if16, g_if16);
    {
        void* tmp;
        cudaGetSymbolAddress(&tmp, g_hu16);
        for (int k = 0; k < 3; ++k) p_hu[k] = (char*)tmp + (size_t)k * NUx * 32 * sizeof(__half2);
        cudaGetSymbolAddress(&tmp, g_hi16);
        for (int k = 0; k < 3; ++k) p_hi[k] = (char*)tmp + (size_t)k * NIx * 32 * sizeof(__half2);
    }

    const int scanb_u = (NUx + SB * SI - 1) / (SB * SI);   // 98
    const int scanb_i = (NIx + SB * SI - 1) / (SB * SI);   // 49

    // ---- CSR build + fp16 input staging ----
    cudaMemsetAsync(p_deg_u, 0, NUx * sizeof(int));
    cudaMemsetAsync(p_deg_i, 0, NIx * sizeof(int));
    k_deg<<<(Ex + 255) / 256, 256>>>(eu, ei);
    k_cvt<<<((NUx + NIx) * 32 + 255) / 256, 256>>>(uf, itf);
    k_scan_blocks<<<scanb_u, SB>>>((const int*)p_deg_u, (int*)p_off_u, (int*)p_bsum_u, NUx);
    k_scan_blocks<<<scanb_i, SB>>>((const int*)p_deg_i, (int*)p_off_i, (int*)p_bsum_i, NIx);
    k_scan_small2<<<2, 128>>>((int*)p_bsum_u, scanb_u, (int*)p_bsum_i, scanb_i);
    k_scan_add<<<scanb_u, SB>>>((int*)p_off_u, (int*)p_cur_u, (const int*)p_bsum_u, NUx);
    k_scan_add<<<scanb_i, SB>>>((int*)p_off_i, (int*)p_cur_i, (const int*)p_bsum_i, NIx);
    k_fill<<<(Ex + 255) / 256, 256>>>(eu, ei);

    const unsigned npairs = (NUx + NIx) / 2;
    const unsigned gagg = (unsigned)(((size_t)npairs * 32 + 255) / 256);

    // ---- 3 propagation layers (both directions merged per launch) ----
    k_agg<<<gagg, 256>>>((const __half2*)p_uf16, (const __half2*)p_if16,
                         (__half2*)p_hu[0], (__half2*)p_hi[0]);
    k_agg<<<gagg, 256>>>((const __half2*)p_hu[0], (const __half2*)p_hi[0],
                         (__half2*)p_hu[1], (__half2*)p_hi[1]);
    k_agg<<<gagg, 256>>>((const __half2*)p_hu[1], (const __half2*)p_hi[1],
                         (__half2*)p_hu[2], (__half2*)p_hi[2]);

    // ---- output gather (e computed on the fly) ----
    k_out<<<(3 * Bx * 16 + 255) / 256, 256>>>(uf, itf, usr, pos, neg, out);
}